// round 14
// baseline (speedup 1.0000x reference)
#include <cuda_runtime.h>
#include <cuda_bf16.h>
#include <cuda_fp16.h>
#include <cstdint>

// ---------------------------------------------------------------------------
// GCN forward. Round 13: tf32 GEMM v2 — A operand loaded directly from global
// (zero reuse => smem staging was pure overhead; X path was 55% L1-bound),
// W in a small double-buffered smem tile. detect merged into init.
//
// Target facts learned:
//  - v4/v2 fp32 atomics trap. Scalar atomicAdd (incl. ull) only.
//  - edge_index encoding ambiguous (int32 vs int64) -> detected on device.
//  - ~1.5-3us per-launch floor: fewer, fatter kernels.
// ---------------------------------------------------------------------------

#define NN 100000
#define NE 1600000
#define FIN 256
#define HID 64
#define NCLS 40

// Scratch (__device__ globals; no allocations allowed)
__device__ float  g_h[(size_t)NN * HID];
__device__ __half g_t[(size_t)NN * HID];
__device__ unsigned long long g_pack[NN];  // cnt<<40 | fixed24(sum ew)
__device__ float  g_dinv[NN];
__device__ int    g_row32[NE];
__device__ int    g_col32[NE];
__device__ int    g_off[NN + 1];
__device__ int    g_cursor[NN];
__device__ int    g_bsum[128];
__device__ int2   g_csr[NE];        // packed {src, float_as_int(w)}
__device__ int    g_is32 = 0;       // monotone: OR-ed by detect; input-determined,
                                    // identical on every replay (idempotent).

__device__ __forceinline__ uint32_t tf32_bits(float x) {
    uint32_t u;
    asm("cvt.rna.tf32.f32 %0, %1;" : "=r"(u) : "f"(x));
    return u;
}
__device__ __forceinline__ float to_tf32(float x) {
    return __uint_as_float(tf32_bits(x));
}

// ---------------- init(+detect) + conversion/count ----------------

// pack=0 everywhere; threads < 65536 also sample odd 32-bit words of the
// edge_index buffer: int64 little-endian small values => odd words all zero;
// any nonzero => buffer is int32.
__global__ void init_detect_k(unsigned long long* __restrict__ pack,
                              const int* __restrict__ buf,
                              int* __restrict__ flag) {
    int i = blockIdx.x * blockDim.x + threadIdx.x;
    if (i < NN) pack[i] = 0ull;
    if (i < 65536 && buf[2 * i + 1] != 0) atomicOr(flag, 1);
}

__global__ void cvt_count_k(const int* __restrict__ buf,
                            const int* __restrict__ flag,
                            const float* __restrict__ ew,
                            int* __restrict__ row32, int* __restrict__ col32,
                            unsigned long long* __restrict__ pack) {
    int e = blockIdx.x * blockDim.x + threadIdx.x;
    if (e < NE) {
        int r, c;
        if (*flag) {
            r = buf[e]; c = buf[NE + e];
        } else {
            const int2* b2 = (const int2*)buf;
            r = b2[e].x;
            c = b2[NE + e].x;
        }
        row32[e] = r;
        col32[e] = c;
        unsigned int q = __float2uint_rn(ew[e] * 16777216.0f);   // 2^24 fixed point
        atomicAdd(&pack[c], (1ull << 40) | (unsigned long long)q);
    }
}

// ---------------- exclusive scan (3 kernels; dinv folded into scan3) --------

__global__ void scan1_k(const unsigned long long* __restrict__ pack,
                        int* __restrict__ off, int* __restrict__ bsum) {
    __shared__ int sh[256];
    int tid = threadIdx.x;
    int base = blockIdx.x * 1024 + tid * 4;
    int v[4];
#pragma unroll
    for (int j = 0; j < 4; j++)
        v[j] = (base + j < NN) ? (int)(pack[base + j] >> 40) : 0;
    int s = v[0] + v[1] + v[2] + v[3];
    sh[tid] = s;
    __syncthreads();
    for (int d = 1; d < 256; d <<= 1) {
        int add = (tid >= d) ? sh[tid - d] : 0;
        __syncthreads();
        sh[tid] += add;
        __syncthreads();
    }
    int run = sh[tid] - s;
#pragma unroll
    for (int j = 0; j < 4; j++) {
        if (base + j < NN) off[base + j] = run;
        run += v[j];
    }
    if (tid == 255) bsum[blockIdx.x] = sh[255];
}

__global__ void scan2_k(int* __restrict__ bsum, int* __restrict__ off, int nblk) {
    __shared__ int sh[128];
    int tid = threadIdx.x;
    int s = (tid < nblk) ? bsum[tid] : 0;
    sh[tid] = s;
    __syncthreads();
    for (int d = 1; d < 128; d <<= 1) {
        int add = (tid >= d) ? sh[tid - d] : 0;
        __syncthreads();
        sh[tid] += add;
        __syncthreads();
    }
    if (tid < nblk) bsum[tid] = sh[tid] - s;
    if (tid == 0) off[NN] = NE;
}

__global__ void scan3_dinv_k(int* __restrict__ off, const int* __restrict__ bsum,
                             int* __restrict__ cursor,
                             const unsigned long long* __restrict__ pack,
                             float* __restrict__ dinv) {
    int i = blockIdx.x * blockDim.x + threadIdx.x;
    if (i < NN) {
        int o = off[i] + bsum[i >> 10];
        off[i] = o;
        cursor[i] = o;
        float d = 1.0f + (float)(double)(pack[i] & 0xFFFFFFFFFFull) * (1.0f / 16777216.0f);
        dinv[i] = rsqrtf(d);   // d >= 1 always
    }
}

__global__ void scatter_k(const int* __restrict__ row32, const int* __restrict__ col32,
                          const float* __restrict__ ew, const float* __restrict__ dinv,
                          int* __restrict__ cursor, int2* __restrict__ csr) {
    int e = blockIdx.x * blockDim.x + threadIdx.x;
    if (e < NE) {
        int r = row32[e];
        int c = col32[e];
        float w = dinv[r] * ew[e] * dinv[c];
        int pos = atomicAdd(&cursor[c], 1);
        int2 p; p.x = r; p.y = __float_as_int(w);
        csr[pos] = p;
    }
}

// ---------------- TF32 GEMM v2: [N,K] @ [K,NOUT<=64] -> [N,NOUT] -----------
// Block 256 thr (8 warps), tile 128 rows x 64 cols, KC=16.
// A frags loaded DIRECTLY from global (each X element consumed once — no
// reuse, so no smem staging). W staged through a double-buffered 16x72 smem
// tile (9.2KB total): one __syncthreads per chunk. fp32 accumulate.

template <int K, int NOUT, bool RELU, bool BIAS, bool HOUT>
__global__ void gemm_tf32(const float* __restrict__ X, const float* __restrict__ W,
                          const float* __restrict__ bias, void* __restrict__ Yv,
                          int N) {
    constexpr int KC = 16;
    constexpr int NK = K / KC;
    constexpr int NV4 = NOUT / 4;
    __shared__ float Ws[2][16][72];    // pad 72: (8tg + 8nt + g) covers 32 banks

    const int tid = threadIdx.x;
    const int wid = tid >> 5;
    const int lane = tid & 31;
    const int g = lane >> 2;
    const int tg = lane & 3;
    const int row0 = blockIdx.x * 128;
    const int wm = wid * 16;

    const int r0g = row0 + wm + g;
    const int r1g = r0g + 8;
    const bool v0 = r0g < N;
    const bool v1 = r1g < N;
    const float* x0 = X + (size_t)(v0 ? r0g : 0) * K;   // safe base if OOB
    const float* x1 = X + (size_t)(v1 ? r1g : 0) * K;

    float c[8][4];
#pragma unroll
    for (int nt = 0; nt < 8; nt++)
#pragma unroll
        for (int j = 0; j < 4; j++) c[nt][j] = 0.0f;

    float4 wr;
    const int wk = tid >> 4;           // 0..15
    const int wc4 = tid & 15;          // 0..15

    auto ldg_w = [&](int kc) {
        if (wc4 < NV4)
            wr = *(const float4*)&W[(size_t)(kc + wk) * NOUT + wc4 * 4];
        else
            wr = make_float4(0.f, 0.f, 0.f, 0.f);
    };
    auto sts_w = [&](int buf) {
        Ws[buf][wk][wc4 * 4 + 0] = to_tf32(wr.x);
        Ws[buf][wk][wc4 * 4 + 1] = to_tf32(wr.y);
        Ws[buf][wk][wc4 * 4 + 2] = to_tf32(wr.z);
        Ws[buf][wk][wc4 * 4 + 3] = to_tf32(wr.w);
    };

    // prologue
    ldg_w(0);
    sts_w(0);
    __syncthreads();

#pragma unroll 4
    for (int i = 0; i < NK; i++) {
        const int kc = i * KC;
        if (i + 1 < NK) ldg_w(kc + KC);     // prefetch next W into regs

        // A frags: thread reads columns kc + tg + 4j (j=0..3) of its 2 rows.
        // Warp = 16 rows x 64B contiguous — full-sector efficiency.
        float a0r[4], a1r[4];
#pragma unroll
        for (int j = 0; j < 4; j++) {
            a0r[j] = v0 ? __ldg(&x0[kc + tg + 4 * j]) : 0.0f;
            a1r[j] = v1 ? __ldg(&x1[kc + tg + 4 * j]) : 0.0f;
        }

        const int buf = i & 1;
#pragma unroll
        for (int kk = 0; kk < 2; kk++) {    // k8 = 8*kk
            const int k8 = kk * 8;
            uint32_t a0 = tf32_bits(a0r[2 * kk + 0]);
            uint32_t a2 = tf32_bits(a0r[2 * kk + 1]);
            uint32_t a1 = tf32_bits(a1r[2 * kk + 0]);
            uint32_t a3 = tf32_bits(a1r[2 * kk + 1]);
#pragma unroll
            for (int nt = 0; nt < 8; nt++) {
                uint32_t b0 = __float_as_uint(Ws[buf][k8 + tg][nt * 8 + g]);
                uint32_t b1 = __float_as_uint(Ws[buf][k8 + tg + 4][nt * 8 + g]);
                asm volatile(
                    "mma.sync.aligned.m16n8k8.row.col.f32.tf32.tf32.f32 "
                    "{%0,%1,%2,%3}, {%4,%5,%6,%7}, {%8,%9}, {%0,%1,%2,%3};"
                    : "+f"(c[nt][0]), "+f"(c[nt][1]), "+f"(c[nt][2]), "+f"(c[nt][3])
                    : "r"(a0), "r"(a1), "r"(a2), "r"(a3), "r"(b0), "r"(b1));
            }
        }
        if (i + 1 < NK) sts_w((i + 1) & 1);  // buffer (i-1)&1: free since last sync
        __syncthreads();
    }

    // Epilogue: thread owns rows (wm+g, wm+g+8), cols nt*8 + 2*tg (+1)
#pragma unroll
    for (int nt = 0; nt < 8; nt++) {
        int n0 = nt * 8 + 2 * tg;
        if (n0 >= NOUT) continue;
        float bx = 0.f, by = 0.f;
        if (BIAS) { bx = __ldg(&bias[n0]); by = __ldg(&bias[n0 + 1]); }
        float2 o0, o1;
        o0.x = c[nt][0] + bx; o0.y = c[nt][1] + by;
        o1.x = c[nt][2] + bx; o1.y = c[nt][3] + by;
        if (RELU) {
            o0.x = fmaxf(o0.x, 0.f); o0.y = fmaxf(o0.y, 0.f);
            o1.x = fmaxf(o1.x, 0.f); o1.y = fmaxf(o1.y, 0.f);
        }
        if (HOUT) {
            __half2* Yh = (__half2*)Yv;
            if (v0) Yh[((size_t)r0g * NOUT + n0) / 2] = __floats2half2_rn(o0.x, o0.y);
            if (v1) Yh[((size_t)r1g * NOUT + n0) / 2] = __floats2half2_rn(o1.x, o1.y);
        } else {
            float* Yf = (float*)Yv;
            if (v0) *(float2*)&Yf[(size_t)r0g * NOUT + n0] = o0;
            if (v1) *(float2*)&Yf[(size_t)r1g * NOUT + n0] = o1;
        }
    }
}

// ---------------- fused CSR aggregation + bias + relu ----------------
// Warp per node, lane = 2 cols (__half2 gather, fp32 accumulate).

__global__ void spmm_csr_k(const int* __restrict__ off,
                           const int2* __restrict__ csr,
                           const __half* __restrict__ t,
                           const float* __restrict__ dinv,
                           const float* __restrict__ bias,
                           float* __restrict__ hout) {
    int n = blockIdx.x * 8 + (threadIdx.x >> 5);
    if (n >= NN) return;
    int lane = threadIdx.x & 31;
    const __half2* t2 = (const __half2*)t;

    float di = __ldg(&dinv[n]);
    float sw = di * di;
    float2 self = __half22float2(t2[(size_t)n * 32 + lane]);
    float accx = self.x * sw;
    float accy = self.y * sw;

    int e = __ldg(&off[n]);
    const int end = __ldg(&off[n + 1]);

    for (; e + 8 <= end; e += 8) {
        int2 p[8];
#pragma unroll
        for (int j = 0; j < 8; j++) p[j] = __ldg(&csr[e + j]);
        __half2 v[8];
#pragma unroll
        for (int j = 0; j < 8; j++) v[j] = t2[(size_t)p[j].x * 32 + lane];
#pragma unroll
        for (int j = 0; j < 8; j++) {
            float w = __int_as_float(p[j].y);
            float2 f = __half22float2(v[j]);
            accx += w * f.x;
            accy += w * f.y;
        }
    }
    if (e + 4 <= end) {
        int2 p[4];
#pragma unroll
        for (int j = 0; j < 4; j++) p[j] = __ldg(&csr[e + j]);
        __half2 v[4];
#pragma unroll
        for (int j = 0; j < 4; j++) v[j] = t2[(size_t)p[j].x * 32 + lane];
#pragma unroll
        for (int j = 0; j < 4; j++) {
            float w = __int_as_float(p[j].y);
            float2 f = __half22float2(v[j]);
            accx += w * f.x;
            accy += w * f.y;
        }
        e += 4;
    }
    for (; e < end; e++) {
        int2 p = __ldg(&csr[e]);
        float w = __int_as_float(p.y);
        float2 f = __half22float2(t2[(size_t)p.x * 32 + lane]);
        accx += w * f.x;
        accy += w * f.y;
    }

    float2 bv = ((const float2*)bias)[lane];
    accx = fmaxf(accx + bv.x, 0.0f);
    accy = fmaxf(accy + bv.y, 0.0f);
    float2 o; o.x = accx; o.y = accy;
    ((float2*)hout)[(size_t)n * 32 + lane] = o;
}

// ---------------- launch ----------------

extern "C" void kernel_launch(void* const* d_in, const int* in_sizes, int n_in,
                              void* d_out, int out_size) {
    const float* x   = (const float*)d_in[0];
    const int*   ei  = (const int*)d_in[1];
    const float* ew  = (const float*)d_in[2];
    const float* W1  = (const float*)d_in[3];
    const float* b1  = (const float*)d_in[4];
    const float* Wc1 = (const float*)d_in[5];
    const float* bc1 = (const float*)d_in[6];
    const float* Wc2 = (const float*)d_in[7];
    const float* bc2 = (const float*)d_in[8];
    const float* W2  = (const float*)d_in[9];
    const float* b2  = (const float*)d_in[10];
    float* out = (float*)d_out;

    float *h, *dinv;
    __half* t;
    unsigned long long* pack;
    int *r32, *c32, *flag, *off, *cursor, *bsum;
    int2 *csr;
    cudaGetSymbolAddress((void**)&h,     g_h);
    cudaGetSymbolAddress((void**)&t,     g_t);
    cudaGetSymbolAddress((void**)&pack,  g_pack);
    cudaGetSymbolAddress((void**)&dinv,  g_dinv);
    cudaGetSymbolAddress((void**)&r32,   g_row32);
    cudaGetSymbolAddress((void**)&c32,   g_col32);
    cudaGetSymbolAddress((void**)&flag,  g_is32);
    cudaGetSymbolAddress((void**)&off,   g_off);
    cudaGetSymbolAddress((void**)&cursor,g_cursor);
    cudaGetSymbolAddress((void**)&bsum,  g_bsum);
    cudaGetSymbolAddress((void**)&csr,   g_csr);

    const int TB = 256;
    const int mma_blocks = (NN + 127) / 128;       // 782
    const int nscan = (NN + 1023) / 1024;          // 98
    const int spmm_blocks = (NN + 7) / 8;          // 12500

    // 1-3: init+detect, convert+count, scan1
    init_detect_k<<<(NN + TB - 1) / TB, TB>>>(pack, ei, flag);
    cvt_count_k<<<(NE + TB - 1) / TB, TB>>>(ei, flag, ew, r32, c32, pack);
    scan1_k<<<nscan, 256>>>(pack, off, bsum);

    // 4: h = relu(x @ W1 + b1) — ncu-captured launch slot.
    gemm_tf32<FIN, HID, true, true, false><<<mma_blocks, TB>>>(x, W1, b1, h, NN);

    // 5-7: finish CSR build
    scan2_k<<<1, 128>>>(bsum, off, nscan);
    scan3_dinv_k<<<(NN + TB - 1) / TB, TB>>>(off, bsum, cursor, pack, dinv);
    scatter_k<<<(NE + TB - 1) / TB, TB>>>(r32, c32, ew, dinv, cursor, csr);

    // conv1: t = h@Wc1 (fp16 out) ; h = relu(S t + bc1)
    gemm_tf32<HID, HID, false, false, true><<<mma_blocks, TB>>>(h, Wc1, nullptr, t, NN);
    spmm_csr_k<<<spmm_blocks, TB>>>(off, csr, t, dinv, bc1, h);

    // conv2
    gemm_tf32<HID, HID, false, false, true><<<mma_blocks, TB>>>(h, Wc2, nullptr, t, NN);
    spmm_csr_k<<<spmm_blocks, TB>>>(off, csr, t, dinv, bc2, h);

    // out = h @ W2 + b2  (tf32, NOUT=40)
    gemm_tf32<HID, NCLS, false, true, false><<<mma_blocks, TB>>>(h, W2, b2, out, NN);
}